// round 2
// baseline (speedup 1.0000x reference)
#include <cuda_runtime.h>

#define T_STEPS 4096
#define BATCH 64
#define IN_DIM 4
#define HID 256
#define OUT_DIM 2

// hidden-state history for the output head: [T, B, H] fp32 = 268 MB scratch
__device__ float g_hs[(size_t)T_STEPS * BATCH * HID];

__device__ __forceinline__ void fma2(unsigned long long &acc,
                                     unsigned long long a,
                                     unsigned long long b) {
    asm("fma.rn.f32x2 %0, %1, %2, %0;" : "+l"(acc) : "l"(a), "l"(b));
}

__device__ __forceinline__ float2 unpack2(unsigned long long v) {
    float2 f;
    asm("mov.b64 {%0, %1}, %2;" : "=f"(f.x), "=f"(f.y) : "l"(v));
    return f;
}

__device__ __forceinline__ unsigned int smem_u32(const void* p) {
    unsigned int a;
    asm("{ .reg .u64 t; cvta.to.shared.u64 t, %1; cvt.u32.u64 %0, t; }"
        : "=r"(a) : "l"(p));
    return a;
}

__device__ __forceinline__ unsigned int mapa_peer(unsigned int laddr,
                                                  unsigned int peer) {
    unsigned int r;
    asm("mapa.shared::cluster.u32 %0, %1, %2;" : "=r"(r) : "r"(laddr), "r"(peer));
    return r;
}

__device__ __forceinline__ void mbar_arrive_remote(unsigned int raddr) {
    // release at cluster scope: publishes this thread's (and, after
    // __syncwarp, this warp's) prior shared::cluster stores
    asm volatile("mbarrier.arrive.release.cluster.shared::cluster.b64 _, [%0];"
                 :: "r"(raddr) : "memory");
}

__device__ __forceinline__ void mbar_wait(unsigned int addr, unsigned int parity) {
    asm volatile(
        "{\n\t"
        ".reg .pred P;\n\t"
        "W_%=:\n\t"
        "mbarrier.try_wait.parity.acquire.cluster.shared::cta.b64 P, [%0], %1, 0x989680;\n\t"
        "@!P bra W_%=;\n\t"
        "}"
        :: "r"(addr), "r"(parity) : "memory");
}

// ---------------------------------------------------------------------------
// Recurrence: 64 clusters x 2 CTAs x 256 threads; cluster c = batch b.
// CTA rank r owns outputs [128r, 128r+128). Output j (local) is computed by
// the lane PAIR (2j, 2j+1): lane 2j+p accumulates K-half p (h[128p..128p+128))
// with its 128 Wh weights held in registers as 64 packed f32x2 values.
// Partial sums are combined with one shfl.xor(1). h is double-buffered in
// SMEM; the remote half arrives via st.shared::cluster, signaled by one
// mbarrier (count=8, one release-arrive per warp) per buffer.
// ---------------------------------------------------------------------------
__global__ void __launch_bounds__(256, 1) __cluster_dims__(2, 1, 1)
elman_recurrence(const float* __restrict__ input,
                 const float* __restrict__ Wi,
                 const float* __restrict__ bi,
                 const float* __restrict__ Wh,
                 const float* __restrict__ bh) {
    __shared__ float hbuf[2][HID];
    __shared__ __align__(8) unsigned long long mbar[2];

    const int tid  = threadIdx.x;
    const int rank = blockIdx.x & 1;
    const int b    = blockIdx.x >> 1;
    const int jl   = tid >> 1;                // local output index 0..127
    const int p    = tid & 1;                 // K-half
    const int jg   = rank * 128 + jl;         // global output index
    const unsigned int peer = rank ^ 1;

    // --- loop-invariant weights into registers ---
    unsigned long long wh[64];
    {
        const ulonglong2* wsrc =
            (const ulonglong2*)(Wh + (size_t)jg * HID + p * 128);
#pragma unroll
        for (int m = 0; m < 32; ++m) {
            ulonglong2 v = __ldg(wsrc + m);
            wh[2 * m]     = v.x;
            wh[2 * m + 1] = v.y;
        }
    }

    // --- per-output constants (same in both lanes of a pair) ---
    const float4 wi4 = __ldg((const float4*)(Wi + (size_t)jg * IN_DIM));
    const float  cb  = __ldg(bi + jg) + __ldg(bh + jg);

    // --- remote addresses (peer CTA) ---
    const unsigned int r_h0 = mapa_peer(smem_u32(&hbuf[0][jg]), peer);
    const unsigned int r_h1 = mapa_peer(smem_u32(&hbuf[1][jg]), peer);
    const unsigned int r_m0 = mapa_peer(smem_u32(&mbar[0]), peer);
    const unsigned int r_m1 = mapa_peer(smem_u32(&mbar[1]), peer);
    const unsigned int l_m0 = smem_u32(&mbar[0]);
    const unsigned int l_m1 = smem_u32(&mbar[1]);

    // --- init: barriers (count = 8 warps) and h0 = 0 ---
    if (tid == 0) {
        asm volatile("mbarrier.init.shared.b64 [%0], %1;" :: "r"(l_m0), "r"(8u) : "memory");
        asm volatile("mbarrier.init.shared.b64 [%0], %1;" :: "r"(l_m1), "r"(8u) : "memory");
    }
    hbuf[0][tid] = 0.f;
    __syncthreads();
    asm volatile("barrier.cluster.arrive.aligned;" ::: "memory");
    asm volatile("barrier.cluster.wait.aligned;" ::: "memory");

    // prime peer's mbar[0] phase 0 (h0 needs no producer)
    if ((tid & 31) == 0) mbar_arrive_remote(r_m0);

    // prefetch input for t=0
    float4 xin = __ldg((const float4*)(input + (size_t)b * IN_DIM));

    float* hsb = g_hs + (size_t)b * HID;

    for (int t = 0; t < T_STEPS; ++t) {
        const int cur = t & 1;
        const unsigned int parity = (t >> 1) & 1;

        // remote half of hbuf[cur] ready?
        mbar_wait(cur ? l_m1 : l_m0, parity);

        // prefetch next step's input (off critical path)
        float4 xnext = xin;
        if (t + 1 < T_STEPS)
            xnext = __ldg((const float4*)(input +
                          ((size_t)(t + 1) * BATCH + b) * IN_DIM));

        // --- dot product over my K-half ---
        const ulonglong2* h2 = ((const ulonglong2*)hbuf[cur]) + p * 32;
        unsigned long long a0 = 0ull, a1 = 0ull, a2 = 0ull, a3 = 0ull;
#pragma unroll
        for (int m = 0; m < 32; m += 2) {
            ulonglong2 hm0 = h2[m];
            fma2(a0, wh[2 * m],     hm0.x);
            fma2(a1, wh[2 * m + 1], hm0.y);
            ulonglong2 hm1 = h2[m + 1];
            fma2(a2, wh[2 * m + 2], hm1.x);
            fma2(a3, wh[2 * m + 3], hm1.y);
        }
        float2 f0 = unpack2(a0), f1 = unpack2(a1);
        float2 f2 = unpack2(a2), f3 = unpack2(a3);
        float partial = ((f0.x + f0.y) + (f1.x + f1.y)) +
                        ((f2.x + f2.y) + (f3.x + f3.y));

        // pair reduction: lanes 2j / 2j+1 exchange partials
        partial += __shfl_xor_sync(0xffffffffu, partial, 1);

        float s  = partial + xin.x * wi4.x + xin.y * wi4.y +
                   xin.z * wi4.z + xin.w * wi4.w + cb;
        float hn = tanhf(s);

        const int nxt = cur ^ 1;
        if (p == 0) {
            hbuf[nxt][jg] = hn;                          // local h_next
            hsb[(size_t)t * (BATCH * HID) + jg] = hn;    // stream hs
        } else {
            unsigned int ra = (nxt ? r_h1 : r_h0);
            asm volatile("st.shared::cluster.f32 [%0], %1;"
                         :: "r"(ra), "f"(hn) : "memory"); // peer h_next
        }

        // publish this warp's remote stores + prove it finished reading cur
        __syncwarp();
        if ((tid & 31) == 0) mbar_arrive_remote(nxt ? r_m1 : r_m0);

        xin = xnext;

        // local-half visibility for next step
        __syncthreads();
    }

    // keep peer alive until last in-flight remote stores/arrives complete
    asm volatile("barrier.cluster.arrive.aligned;" ::: "memory");
    asm volatile("barrier.cluster.wait.aligned;" ::: "memory");
}

// ---------------------------------------------------------------------------
// Output head: out[t,b,:] = tanh(hs[t,b,:] @ Wf^T + bf). One warp per row,
// grid-stride; memory-bound (streams 268 MB of hs).
// ---------------------------------------------------------------------------
__global__ void __launch_bounds__(256)
elman_head(const float* __restrict__ Wf,
           const float* __restrict__ bf,
           float* __restrict__ out) {
    const int lane   = threadIdx.x & 31;
    const int gwarp  = (blockIdx.x * blockDim.x + threadIdx.x) >> 5;
    const int nwarps = (gridDim.x * blockDim.x) >> 5;

    const float bf0 = __ldg(bf + 0);
    const float bf1 = __ldg(bf + 1);

    const float4* wf0p = (const float4*)(Wf) + lane * 2;
    const float4* wf1p = (const float4*)(Wf + HID) + lane * 2;
    const float4 w00 = __ldg(wf0p), w01 = __ldg(wf0p + 1);
    const float4 w10 = __ldg(wf1p), w11 = __ldg(wf1p + 1);

    const int nrows = T_STEPS * BATCH;
    for (int row = gwarp; row < nrows; row += nwarps) {
        const float4* h = (const float4*)(g_hs + (size_t)row * HID) + lane * 2;
        float4 h0 = h[0], h1 = h[1];
        float s0 = h0.x * w00.x + h0.y * w00.y + h0.z * w00.z + h0.w * w00.w +
                   h1.x * w01.x + h1.y * w01.y + h1.z * w01.z + h1.w * w01.w;
        float s1 = h0.x * w10.x + h0.y * w10.y + h0.z * w10.z + h0.w * w10.w +
                   h1.x * w11.x + h1.y * w11.y + h1.z * w11.z + h1.w * w11.w;
#pragma unroll
        for (int o = 16; o; o >>= 1) {
            s0 += __shfl_xor_sync(0xffffffffu, s0, o);
            s1 += __shfl_xor_sync(0xffffffffu, s1, o);
        }
        if (lane == 0) {
            out[(size_t)row * OUT_DIM + 0] = tanhf(s0 + bf0);
            out[(size_t)row * OUT_DIM + 1] = tanhf(s1 + bf1);
        }
    }
}

extern "C" void kernel_launch(void* const* d_in, const int* in_sizes, int n_in,
                              void* d_out, int out_size) {
    // metadata order: input, target, Wi, bi, Wh, bh, Wf, bf
    const float* input = (const float*)d_in[0];
    const float* Wi = (const float*)d_in[2];
    const float* bi = (const float*)d_in[3];
    const float* Wh = (const float*)d_in[4];
    const float* bh = (const float*)d_in[5];
    const float* Wf = (const float*)d_in[6];
    const float* bf = (const float*)d_in[7];
    float* out = (float*)d_out;

    elman_recurrence<<<2 * BATCH, 256>>>(input, Wi, bi, Wh, bh);
    elman_head<<<1024, 256>>>(Wf, bf, out);
}

// round 4
// speedup vs baseline: 1.2476x; 1.2476x over previous
#include <cuda_runtime.h>

#define T_STEPS 4096
#define BATCH 64
#define IN_DIM 4
#define HID 256
#define OUT_DIM 2

// hidden-state history for the output head: [T, B, H] fp32 = 268 MB scratch
__device__ float g_hs[(size_t)T_STEPS * BATCH * HID];

__device__ __forceinline__ void fma2(unsigned long long &acc,
                                     unsigned long long a,
                                     unsigned long long b) {
    asm("fma.rn.f32x2 %0, %1, %2, %0;" : "+l"(acc) : "l"(a), "l"(b));
}

__device__ __forceinline__ float2 unpack2(unsigned long long v) {
    float2 f;
    asm("mov.b64 {%0, %1}, %2;" : "=f"(f.x), "=f"(f.y) : "l"(v));
    return f;
}

__device__ __forceinline__ unsigned int smem_u32(const void* p) {
    unsigned int a;
    asm("{ .reg .u64 t; cvta.to.shared.u64 t, %1; cvt.u32.u64 %0, t; }"
        : "=r"(a) : "l"(p));
    return a;
}

__device__ __forceinline__ unsigned int mapa_peer(unsigned int laddr,
                                                  unsigned int peer) {
    unsigned int r;
    asm("mapa.shared::cluster.u32 %0, %1, %2;" : "=r"(r) : "r"(laddr), "r"(peer));
    return r;
}

// ---------------------------------------------------------------------------
// Recurrence, K-split across a 2-CTA cluster. Cluster c = batch b.
// CTA rank r owns k-range [128r, 128r+128) of h and finalizes outputs j in
// the SAME range (so its next-step inputs are exactly what it produced).
// Every thread computes the K-half partial of ONE output j (its 128 Wh
// weights resident in 64 f32x2 registers):
//   warps 4..7 (hi-wid, issue priority): j in PEER range -> partial stored
//       into peer's pbuf via st.shared::cluster + one release-arrive per
//       warp on the peer's mbarrier (count=4).
//   warps 0..3: j in LOCAL range -> partial + xi + bias; try_wait
//       (acquire.cluster) for incoming partials; add, tanh, store h + g_hs.
// DSMEM transit (~215cy) overlaps the local warps' FMA work.
// One __syncthreads per step; no cluster barrier in the loop.
// ---------------------------------------------------------------------------
__global__ void __launch_bounds__(256, 1) __cluster_dims__(2, 1, 1)
elman_recurrence(const float* __restrict__ input,
                 const float* __restrict__ Wi,
                 const float* __restrict__ bi,
                 const float* __restrict__ Wh,
                 const float* __restrict__ bh) {
    __shared__ float hbuf[2][128];   // local half of h (double-buffered)
    __shared__ float pbuf[2][128];   // incoming peer partials (double-buffered)
    __shared__ __align__(8) unsigned long long mbar[2];

    const int tid  = threadIdx.x;
    const int rank = blockIdx.x & 1;
    const int b    = blockIdx.x >> 1;
    const unsigned int peer = rank ^ 1;
    const bool is_local = (tid < 128);          // warps 0-3 finalize local outputs
    const int  li = tid & 127;

    // output row this thread computes the K-half partial for
    const int j_out = (is_local ? 128 * rank : 128 * (1 - rank)) + li;

    // --- loop-invariant weights Wh[j_out][128*rank .. +128) in registers ---
    unsigned long long wh[64];
    {
        const ulonglong2* wsrc =
            (const ulonglong2*)(Wh + (size_t)j_out * HID + rank * 128);
#pragma unroll
        for (int m = 0; m < 32; ++m) {
            ulonglong2 v = __ldg(wsrc + m);
            wh[2 * m]     = v.x;
            wh[2 * m + 1] = v.y;
        }
    }

    // --- finalizer constants (local role only) ---
    float4 wi4 = make_float4(0.f, 0.f, 0.f, 0.f);
    float  cb  = 0.f;
    if (is_local) {
        wi4 = __ldg((const float4*)(Wi + (size_t)j_out * IN_DIM));
        cb  = __ldg(bi + j_out) + __ldg(bh + j_out);
    }

    // --- remote addresses (outgoing role): peer's pbuf slot + mbar ---
    unsigned int r_pb0 = 0, r_pb1 = 0, r_mb0 = 0, r_mb1 = 0;
    if (!is_local) {
        r_pb0 = mapa_peer(smem_u32(&pbuf[0][li]), peer);
        r_pb1 = mapa_peer(smem_u32(&pbuf[1][li]), peer);
        r_mb0 = mapa_peer(smem_u32(&mbar[0]), peer);
        r_mb1 = mapa_peer(smem_u32(&mbar[1]), peer);
    }
    const unsigned int l_mb0 = smem_u32(&mbar[0]);
    const unsigned int l_mb1 = smem_u32(&mbar[1]);

    // --- init: mbarriers (4 arrives = one per outgoing warp), h0 = 0 ---
    if (tid == 0) {
        asm volatile("mbarrier.init.shared.b64 [%0], %1;" :: "r"(l_mb0), "r"(4u) : "memory");
        asm volatile("mbarrier.init.shared.b64 [%0], %1;" :: "r"(l_mb1), "r"(4u) : "memory");
    }
    if (is_local) hbuf[0][li] = 0.f;
    __syncthreads();
    // peer must see our mbar init + hbuf before its step-0 remote stores
    asm volatile("barrier.cluster.arrive.aligned;" ::: "memory");
    asm volatile("barrier.cluster.wait.aligned;" ::: "memory");

    // prefetch xi input for t=0 (local role)
    float4 xin = make_float4(0.f, 0.f, 0.f, 0.f);
    if (is_local)
        xin = __ldg((const float4*)(input + (size_t)b * IN_DIM));

    // this thread's hs stream slot: g_hs[t][b][j_out]
    float* hsb = g_hs + (size_t)b * HID + j_out - 128 * rank + 128 * rank; // = b*HID + j_out... keep simple below
    hsb = g_hs + (size_t)b * HID + (size_t)j_out;

    for (int t = 0; t < T_STEPS; ++t) {
        const int cur = t & 1;
        const unsigned int par = (t >> 1) & 1;

        // prefetch next xi early (independent; hides L1/L2 latency)
        float4 xnext = xin;
        if (is_local && t + 1 < T_STEPS)
            xnext = __ldg((const float4*)(input +
                          ((size_t)(t + 1) * BATCH + b) * IN_DIM));

        // --- K-half dot product over local h (broadcast LDS.128) ---
        const ulonglong2* h2 = (const ulonglong2*)hbuf[cur];
        unsigned long long a0 = 0ull, a1 = 0ull, a2 = 0ull, a3 = 0ull;
#pragma unroll
        for (int m = 0; m < 32; m += 2) {
            ulonglong2 hm0 = h2[m];
            fma2(a0, wh[2 * m],     hm0.x);
            fma2(a1, wh[2 * m + 1], hm0.y);
            ulonglong2 hm1 = h2[m + 1];
            fma2(a2, wh[2 * m + 2], hm1.x);
            fma2(a3, wh[2 * m + 3], hm1.y);
        }
        float2 f0 = unpack2(a0), f1 = unpack2(a1);
        float2 f2 = unpack2(a2), f3 = unpack2(a3);
        float partial = ((f0.x + f0.y) + (f1.x + f1.y)) +
                        ((f2.x + f2.y) + (f3.x + f3.y));

        if (!is_local) {
            // ship partial to peer's pbuf[cur][li], then signal (per warp)
            asm volatile("st.shared::cluster.f32 [%0], %1;"
                         :: "r"(cur ? r_pb1 : r_pb0), "f"(partial) : "memory");
            __syncwarp();
            if ((tid & 31) == 0)
                asm volatile("mbarrier.arrive.release.cluster.shared::cluster.b64 _, [%0];"
                             :: "r"(cur ? r_mb1 : r_mb0) : "memory");
        } else {
            // fold in xi while the peer's partial is in flight
            float pre = partial + xin.x * wi4.x + xin.y * wi4.y +
                        xin.z * wi4.z + xin.w * wi4.w + cb;

            // wait for the peer's 4 warp-arrives on this buffer.
            // acquire.cluster: the matching release is from the peer CTA, so
            // the acquire scope must span the cluster.
            asm volatile(
                "{\n\t"
                ".reg .pred P;\n\t"
                "W_%=:\n\t"
                "mbarrier.try_wait.parity.acquire.cluster.shared::cta.b64 P, [%0], %1, 0x989680;\n\t"
                "@!P bra W_%=;\n\t"
                "}"
                :: "r"(cur ? l_mb1 : l_mb0), "r"(par) : "memory");

            float hn = tanhf(pre + pbuf[cur][li]);
            hbuf[cur ^ 1][li] = hn;                          // next-step local h
            hsb[(size_t)t * (BATCH * HID)] = hn;             // g_hs[t][b][j_out]
            xin = xnext;
        }

        // local visibility of hbuf[nxt] for all 8 warps
        __syncthreads();
    }

    // keep cluster alive until last in-flight remote stores/arrives land
    asm volatile("barrier.cluster.arrive.aligned;" ::: "memory");
    asm volatile("barrier.cluster.wait.aligned;" ::: "memory");
}

// ---------------------------------------------------------------------------
// Output head: out[t,b,:] = tanh(hs[t,b,:] @ Wf^T + bf). One warp per row,
// grid-stride; memory-bound (streams 268 MB of hs at ~60% of HBM peak).
// ---------------------------------------------------------------------------
__global__ void __launch_bounds__(256)
elman_head(const float* __restrict__ Wf,
           const float* __restrict__ bf,
           float* __restrict__ out) {
    const int lane   = threadIdx.x & 31;
    const int gwarp  = (blockIdx.x * blockDim.x + threadIdx.x) >> 5;
    const int nwarps = (gridDim.x * blockDim.x) >> 5;

    const float bf0 = __ldg(bf + 0);
    const float bf1 = __ldg(bf + 1);

    const float4* wf0p = (const float4*)(Wf) + lane * 2;
    const float4* wf1p = (const float4*)(Wf + HID) + lane * 2;
    const float4 w00 = __ldg(wf0p), w01 = __ldg(wf0p + 1);
    const float4 w10 = __ldg(wf1p), w11 = __ldg(wf1p + 1);

    const int nrows = T_STEPS * BATCH;
    for (int row = gwarp; row < nrows; row += nwarps) {
        const float4* h = (const float4*)(g_hs + (size_t)row * HID) + lane * 2;
        float4 h0 = h[0], h1 = h[1];
        float s0 = h0.x * w00.x + h0.y * w00.y + h0.z * w00.z + h0.w * w00.w +
                   h1.x * w01.x + h1.y * w01.y + h1.z * w01.z + h1.w * w01.w;
        float s1 = h0.x * w10.x + h0.y * w10.y + h0.z * w10.z + h0.w * w10.w +
                   h1.x * w11.x + h1.y * w11.y + h1.z * w11.z + h1.w * w11.w;
#pragma unroll
        for (int o = 16; o; o >>= 1) {
            s0 += __shfl_xor_sync(0xffffffffu, s0, o);
            s1 += __shfl_xor_sync(0xffffffffu, s1, o);
        }
        if (lane == 0) {
            out[(size_t)row * OUT_DIM + 0] = tanhf(s0 + bf0);
            out[(size_t)row * OUT_DIM + 1] = tanhf(s1 + bf1);
        }
    }
}

extern "C" void kernel_launch(void* const* d_in, const int* in_sizes, int n_in,
                              void* d_out, int out_size) {
    // metadata order: input, target, Wi, bi, Wh, bh, Wf, bf
    const float* input = (const float*)d_in[0];
    const float* Wi = (const float*)d_in[2];
    const float* bi = (const float*)d_in[3];
    const float* Wh = (const float*)d_in[4];
    const float* bh = (const float*)d_in[5];
    const float* Wf = (const float*)d_in[6];
    const float* bf = (const float*)d_in[7];
    float* out = (float*)d_out;

    elman_recurrence<<<2 * BATCH, 256>>>(input, Wi, bi, Wh, bh);
    elman_head<<<1024, 256>>>(Wf, bf, out);
}